// round 12
// baseline (speedup 1.0000x reference)
#include <cuda_runtime.h>

#define NN    50000
#define DD    128
#define EE    600000
#define NPRED 200000
#define NSEL  300000
#define UD    256
#define NB    49          // scan blocks: 49*1024 >= NN
#define NSM   148
#define NT64  ((NN + 63) / 64)   // 782 row-tiles

typedef unsigned long long ull;

// packed f32x2 helpers (sm_103a FFMA2 — only reachable via PTX)
#define FMA2(d, a, b) asm("fma.rn.f32x2 %0, %1, %2, %0;" : "+l"(d) : "l"(a), "l"(b))
#define UNPACK2(lo, hi, s) asm("mov.b64 {%0, %1}, %2;" : "=f"(lo), "=f"(hi) : "l"(s))

// PDL: wait = no-op when launched without the PSS attribute (safe fallback)
#define GWAIT() asm volatile("griddepcontrol.wait;" ::: "memory")
#define GTRIG() asm volatile("griddepcontrol.launch_dependents;" ::: "memory")

// ---------------- scratch (device globals: allocation-free) ----------------
__device__ int   g_deg_in[NN];
__device__ int   g_deg_out[NN];
__device__ float g_rin[NN];
__device__ float g_rout[NN];
__device__ int   g_off[NN + 1];
__device__ int   g_cur[NN];
__device__ int   g_srcs[EE];
__device__ int   g_bsum[NB];
__device__ float g_bufA[(size_t)NN * DD];
__device__ float g_bufB[(size_t)NN * DD];
__device__ float g_part[(size_t)NN * 4];   // [node][half*2 + {p0,p1}]

// ---------------- degree counting ----------------
__global__ void k_zero() {
    int i = blockIdx.x * blockDim.x + threadIdx.x;
    if (i < NN) { g_deg_in[i] = 0; g_deg_out[i] = 0; }
    GTRIG();
}

__global__ void k_count(const int* __restrict__ ei) {
    int e = blockIdx.x * blockDim.x + threadIdx.x;
    int s = 0, d = 0;
    if (e < EE) { s = ei[e]; d = ei[EE + e]; }   // prologue: inputs only
    GWAIT();
    if (e < EE) {
        atomicAdd(&g_deg_out[s], 1);
        atomicAdd(&g_deg_in[d], 1);
    }
    GTRIG();
}

// ---------------- scan pass A (+ fused rsqrt) ----------------
__global__ void k_scan_a(int unused) {
    __shared__ int wsum[32];
    GWAIT();
    int tid  = threadIdx.x;
    int i    = blockIdx.x * 1024 + tid;
    int lane = tid & 31, wid = tid >> 5;
    int v = (i < NN) ? g_deg_in[i] : 0;

    if (i < NN) {
        int dout = g_deg_out[i]; if (dout < 1) dout = 1;
        int din  = v;            if (din  < 1) din  = 1;
        g_rout[i] = rsqrtf((float)dout);
        g_rin[i]  = rsqrtf((float)din);
    }

    int x = v;
    #pragma unroll
    for (int s = 1; s < 32; s <<= 1) {
        int t = __shfl_up_sync(0xffffffffu, x, s);
        if (lane >= s) x += t;
    }
    if (lane == 31) wsum[wid] = x;
    __syncthreads();
    if (wid == 0) {
        int y = wsum[lane];
        #pragma unroll
        for (int s = 1; s < 32; s <<= 1) {
            int t = __shfl_up_sync(0xffffffffu, y, s);
            if (lane >= s) y += t;
        }
        wsum[lane] = y;
    }
    __syncthreads();

    int excl = x - v + (wid ? wsum[wid - 1] : 0);
    if (i < NN) g_off[i] = excl;
    if (tid == 1023) g_bsum[blockIdx.x] = excl + v;
    GTRIG();
}

// ---------------- scan pass C ----------------
__global__ void k_scan_c(int unused) {
    __shared__ int s_pre;
    GWAIT();
    int tid = threadIdx.x;
    if (tid == 0) {
        int run = 0;
        #pragma unroll
        for (int b = 0; b < NB; b++) {
            if (b == blockIdx.x) s_pre = run;
            run += g_bsum[b];
        }
        if (blockIdx.x == 0) g_off[NN] = run;
    }
    __syncthreads();
    int i = blockIdx.x * 1024 + tid;
    if (i < NN) {
        int o = g_off[i] + s_pre;
        g_off[i] = o;
        g_cur[i] = o;
    }
    GTRIG();
}

// ---------------- CSR fill ----------------
__global__ void k_fill(const int* __restrict__ ei) {
    int e = blockIdx.x * blockDim.x + threadIdx.x;
    int s = 0, d = 0;
    if (e < EE) { s = ei[e]; d = ei[EE + e]; }   // prologue: inputs only
    GWAIT();
    if (e < EE) {
        int slot = atomicAdd(&g_cur[d], 1);
        g_srcs[slot] = s;
    }
    GTRIG();
}

// ---------------- conv GEMM (persistent, k-pair f32x2): dst = (X*rout)@W -----
// grid 2*NSM x 256 thr, 2 CTA/SM. A k-values loaded 4-wide (1 bcast LDS.128
// per row per kp-pair) -> LDS 384 vs FMA2 512 cyc/SM/2kp: FMA2 is sole bound.
__global__ void __launch_bounds__(256, 2)
k_gemm(const float* __restrict__ Xext, const float* __restrict__ W,
       float* __restrict__ dst, int useB) {
    extern __shared__ float sm[];
    float* Ws2 = sm;              // 64 kp x 128 cols x float2 (64 KB)
    float* Xs  = sm + DD * DD;    // 64 x 128
    const float* X = useB ? (const float*)g_bufB : Xext;

    int tid = threadIdx.x, wid = tid >> 5, lane = tid & 31;

    {   // prologue (independent): stage W k-pair interleaved
        float2* Wd = (float2*)Ws2;
        #pragma unroll
        for (int q = 0; q < 32; q++) {
            int idx = tid + 256 * q;
            int kp = idx >> 7, c = idx & 127;
            Wd[idx] = make_float2(W[(2 * kp) * DD + c], W[(2 * kp + 1) * DD + c]);
        }
    }
    __syncthreads();
    GWAIT();
    const ull* Wp = (const ull*)Ws2;

    for (int tile = blockIdx.x; tile < NT64; tile += 2 * NSM) {
        int m0 = tile * 64;
        #pragma unroll
        for (int q = 0; q < 8; q++) {
            int gi = m0 + wid * 8 + q;
            float4 v = make_float4(0.f, 0.f, 0.f, 0.f);
            if (gi < NN) {
                v = *(const float4*)(X + (size_t)gi * DD + 4 * lane);
                float sc = g_rout[gi];
                v.x *= sc; v.y *= sc; v.z *= sc; v.w *= sc;
            }
            *(float4*)(Xs + (wid * 8 + q) * DD + 4 * lane) = v;
        }
        __syncwarp();

        ull acc[8][4];
        #pragma unroll
        for (int r = 0; r < 8; r++)
            #pragma unroll
            for (int c = 0; c < 4; c++) acc[r][c] = 0ull;

        #pragma unroll 2
        for (int kp2 = 0; kp2 < DD / 4; kp2++) {     // two k-pairs per iter
            const ull* base = Wp + (2 * kp2) * DD + 4 * lane;
            ulonglong2 b00 = *(const ulonglong2*)(base);
            ulonglong2 b01 = *(const ulonglong2*)(base + 2);
            ulonglong2 b10 = *(const ulonglong2*)(base + DD);
            ulonglong2 b11 = *(const ulonglong2*)(base + DD + 2);
            #pragma unroll
            for (int r = 0; r < 8; r++) {
                ulonglong2 aa = *(const ulonglong2*)(Xs + (wid * 8 + r) * DD + 4 * kp2);
                FMA2(acc[r][0], aa.x, b00.x);
                FMA2(acc[r][1], aa.x, b00.y);
                FMA2(acc[r][2], aa.x, b01.x);
                FMA2(acc[r][3], aa.x, b01.y);
                FMA2(acc[r][0], aa.y, b10.x);
                FMA2(acc[r][1], aa.y, b10.y);
                FMA2(acc[r][2], aa.y, b11.x);
                FMA2(acc[r][3], aa.y, b11.y);
            }
        }

        #pragma unroll
        for (int r = 0; r < 8; r++) {
            int gi = m0 + wid * 8 + r;
            if (gi < NN) {
                float4 o;
                float lo, hi;
                UNPACK2(lo, hi, acc[r][0]); o.x = lo + hi;
                UNPACK2(lo, hi, acc[r][1]); o.y = lo + hi;
                UNPACK2(lo, hi, acc[r][2]); o.z = lo + hi;
                UNPACK2(lo, hi, acc[r][3]); o.w = lo + hi;
                *(float4*)(dst + (size_t)gi * DD + 4 * lane) = o;
            }
        }
        __syncwarp();
    }
    GTRIG();
}

// ---------------- aggregation (separate, high-occupancy): bufB = rin*agg(bufA)+b
__global__ void k_agg(const float* __restrict__ bias) {
    int t = blockIdx.x * blockDim.x + threadIdx.x;
    int w = t >> 5, lane = t & 31;
    float4 bb = *(const float4*)(bias + (t & 31) * 4);   // prologue: input only
    GWAIT();
    if (w >= NN) { GTRIG(); return; }
    int lo = g_off[w], hi = g_off[w + 1];
    float4 acc = make_float4(0.f, 0.f, 0.f, 0.f);
    for (int j = lo; j < hi; j++) {
        int s = g_srcs[j];
        float4 v = *(const float4*)(g_bufA + (size_t)s * DD + lane * 4);
        acc.x += v.x; acc.y += v.y; acc.z += v.z; acc.w += v.w;
    }
    float r = g_rin[w];
    float4 o;
    o.x = acc.x * r + bb.x; o.y = acc.y * r + bb.y;
    o.z = acc.z * r + bb.z; o.w = acc.w * r + bb.w;
    *(float4*)(g_bufB + (size_t)w * DD + lane * 4) = o;
    GTRIG();
}

// ---------------- dense head, HALF-SPLIT: 2 CTA/SM, each CTA owns 128 cols ---
__global__ void __launch_bounds__(256, 2)
k_dense(const float* __restrict__ dW,
        const float* __restrict__ db,
        const float* __restrict__ oW) {
    extern __shared__ float sm[];
    float* Ws2  = sm;                  // 64 kp x 128 cols x float2 (64 KB)
    float* Xs   = Ws2 + DD * DD;       // 64 x 128 (32 KB)
    float* s_db = Xs + 64 * DD;        // 128
    float* s_oW = s_db + 128;          // 256

    int tid  = threadIdx.x, wid = tid >> 5, lane = tid & 31;
    int half = blockIdx.x & 1;
    int cbase = half * 128;

    {   // prologue (independent): stage this half of dense_W + biases
        float2* Wd = (float2*)Ws2;
        #pragma unroll
        for (int q = 0; q < 32; q++) {
            int idx = tid + 256 * q;          // 0..8191
            int kp = idx >> 7, c = idx & 127;
            Wd[idx] = make_float2(dW[(2 * kp) * UD + cbase + c],
                                  dW[(2 * kp + 1) * UD + cbase + c]);
        }
    }
    if (tid < 128) {
        s_db[tid]         = db[cbase + tid];
        s_oW[tid * 2]     = oW[(cbase + tid) * 2];
        s_oW[tid * 2 + 1] = oW[(cbase + tid) * 2 + 1];
    }
    __syncthreads();
    GWAIT();
    const ull* Wp = (const ull*)Ws2;

    for (int tile = blockIdx.x >> 1; tile < NT64; tile += NSM) {
        int m0 = tile * 64;
        #pragma unroll
        for (int q = 0; q < 8; q++) {
            int gi = m0 + wid * 8 + q;
            float4 v = make_float4(0.f, 0.f, 0.f, 0.f);
            if (gi < NN)
                v = *(const float4*)(g_bufB + (size_t)gi * DD + 4 * lane);
            *(float4*)(Xs + (wid * 8 + q) * DD + 4 * lane) = v;
        }
        __syncwarp();

        ull acc[8][4];
        #pragma unroll
        for (int r = 0; r < 8; r++)
            #pragma unroll
            for (int c = 0; c < 4; c++) acc[r][c] = 0ull;

        #pragma unroll 2
        for (int kp2 = 0; kp2 < DD / 4; kp2++) {
            const ull* base = Wp + (2 * kp2) * DD + 4 * lane;
            ulonglong2 b00 = *(const ulonglong2*)(base);
            ulonglong2 b01 = *(const ulonglong2*)(base + 2);
            ulonglong2 b10 = *(const ulonglong2*)(base + DD);
            ulonglong2 b11 = *(const ulonglong2*)(base + DD + 2);
            #pragma unroll
            for (int r = 0; r < 8; r++) {
                ulonglong2 aa = *(const ulonglong2*)(Xs + (wid * 8 + r) * DD + 4 * kp2);
                FMA2(acc[r][0], aa.x, b00.x);
                FMA2(acc[r][1], aa.x, b00.y);
                FMA2(acc[r][2], aa.x, b01.x);
                FMA2(acc[r][3], aa.x, b01.y);
                FMA2(acc[r][0], aa.y, b10.x);
                FMA2(acc[r][1], aa.y, b10.y);
                FMA2(acc[r][2], aa.y, b11.x);
                FMA2(acc[r][3], aa.y, b11.y);
            }
        }

        // epilogue: relu + partial 128->2, warp reduce, write g_part
        #pragma unroll
        for (int r = 0; r < 8; r++) {
            float p0 = 0.f, p1 = 0.f;
            #pragma unroll
            for (int c = 0; c < 4; c++) {
                float lo, hi;
                UNPACK2(lo, hi, acc[r][c]);
                int col = 4 * lane + c;               // col within half
                float v = fmaxf(lo + hi + s_db[col], 0.f);
                p0 = fmaf(v, s_oW[col * 2],     p0);
                p1 = fmaf(v, s_oW[col * 2 + 1], p1);
            }
            #pragma unroll
            for (int o = 16; o; o >>= 1) {
                p0 += __shfl_down_sync(0xffffffffu, p0, o);
                p1 += __shfl_down_sync(0xffffffffu, p1, o);
            }
            if (lane == 0) {
                int gi = m0 + wid * 8 + r;
                if (gi < NN)
                    *(float2*)(g_part + (size_t)gi * 4 + half * 2) = make_float2(p0, p1);
            }
        }
        __syncwarp();
    }
    GTRIG();
}

// ---------------- output: combine halves + ob + softmax + gather -------------
__global__ void k_out(const int* __restrict__ set_idx,
                      const int* __restrict__ oe,
                      const float* __restrict__ ob,
                      float* __restrict__ out) {
    int i = blockIdx.x * blockDim.x + threadIdx.x;
    int node = 0;
    float ob0 = ob[0], ob1 = ob[1];
    if (i < NSEL) node = oe[set_idx[i]];          // prologue: inputs only
    GWAIT();
    if (i < NSEL) {
        float4 pt = *(const float4*)(g_part + (size_t)node * 4);
        float z0 = pt.x + pt.z + ob0;
        float z1 = pt.y + pt.w + ob1;
        float m  = fmaxf(z0, z1);
        float e0 = __expf(z0 - m), e1 = __expf(z1 - m);
        float inv = 1.f / (e0 + e1);
        *(float2*)(out + (size_t)i * 2) = make_float2(e0 * inv, e1 * inv);
    }
}

// ---------------- host launch ----------------
extern "C" void kernel_launch(void* const* d_in, const int* in_sizes, int n_in,
                              void* d_out, int out_size) {
    const float* node_state = (const float*)d_in[0];
    const int*   edge_index = (const int*)d_in[1];
    const int*   out_edges  = (const int*)d_in[2];
    const int*   set_idx    = (const int*)d_in[3];
    const float* W1         = (const float*)d_in[4];
    const float* b1         = (const float*)d_in[5];
    const float* W2         = (const float*)d_in[6];
    const float* b2         = (const float*)d_in[7];
    const float* dW         = (const float*)d_in[8];
    const float* db         = (const float*)d_in[9];
    const float* oW         = (const float*)d_in[10];
    const float* ob         = (const float*)d_in[11];
    float* out = (float*)d_out;

    const int GEMM_SMEM  = (DD * DD + 64 * DD) * 4;                // 96 KB
    const int DENSE_SMEM = (DD * DD + 64 * DD + 128 + 256) * 4;    // ~97.5 KB

    cudaFuncSetAttribute(k_gemm,  cudaFuncAttributeMaxDynamicSharedMemorySize, GEMM_SMEM);
    cudaFuncSetAttribute(k_dense, cudaFuncAttributeMaxDynamicSharedMemorySize, DENSE_SMEM);

    float* bufA = nullptr; float* bufB = nullptr;
    cudaGetSymbolAddress((void**)&bufA, g_bufA);
    cudaGetSymbolAddress((void**)&bufB, g_bufB);

    // PDL launch config (programmatic stream serialization); fallback = plain.
    cudaLaunchAttribute pss;
    pss.id = cudaLaunchAttributeProgrammaticStreamSerialization;
    pss.val.programmaticStreamSerializationAllowed = 1;
    auto cfg = [&](unsigned gx, unsigned bx, unsigned smem) {
        cudaLaunchConfig_t c = {};
        c.gridDim = dim3(gx, 1, 1); c.blockDim = dim3(bx, 1, 1);
        c.dynamicSmemBytes = smem; c.stream = 0;
        c.attrs = &pss; c.numAttrs = 1;
        return c;
    };

    k_zero<<<(NN + 1023) / 1024, 1024>>>();

    {   cudaLaunchConfig_t c = cfg((EE + 255) / 256, 256, 0);
        if (cudaLaunchKernelEx(&c, k_count, edge_index) != cudaSuccess)
            { cudaGetLastError(); k_count<<<(EE + 255) / 256, 256>>>(edge_index); } }
    {   cudaLaunchConfig_t c = cfg(NB, 1024, 0);
        if (cudaLaunchKernelEx(&c, k_scan_a, 0) != cudaSuccess)
            { cudaGetLastError(); k_scan_a<<<NB, 1024>>>(0); } }
    {   cudaLaunchConfig_t c = cfg(NB, 1024, 0);
        if (cudaLaunchKernelEx(&c, k_scan_c, 0) != cudaSuccess)
            { cudaGetLastError(); k_scan_c<<<NB, 1024>>>(0); } }
    {   cudaLaunchConfig_t c = cfg((EE + 255) / 256, 256, 0);
        if (cudaLaunchKernelEx(&c, k_fill, edge_index) != cudaSuccess)
            { cudaGetLastError(); k_fill<<<(EE + 255) / 256, 256>>>(edge_index); } }

    {   cudaLaunchConfig_t c = cfg(2 * NSM, 256, GEMM_SMEM);
        if (cudaLaunchKernelEx(&c, k_gemm, node_state, W1, bufA, 0) != cudaSuccess)
            { cudaGetLastError(); k_gemm<<<2 * NSM, 256, GEMM_SMEM>>>(node_state, W1, bufA, 0); } }
    {   cudaLaunchConfig_t c = cfg((NN * 32 + 255) / 256, 256, 0);
        if (cudaLaunchKernelEx(&c, k_agg, b1) != cudaSuccess)
            { cudaGetLastError(); k_agg<<<(NN * 32 + 255) / 256, 256>>>(b1); } }
    {   cudaLaunchConfig_t c = cfg(2 * NSM, 256, GEMM_SMEM);
        if (cudaLaunchKernelEx(&c, k_gemm, (const float*)nullptr, W2, bufA, 1) != cudaSuccess)
            { cudaGetLastError(); k_gemm<<<2 * NSM, 256, GEMM_SMEM>>>(nullptr, W2, bufA, 1); } }
    {   cudaLaunchConfig_t c = cfg((NN * 32 + 255) / 256, 256, 0);
        if (cudaLaunchKernelEx(&c, k_agg, b2) != cudaSuccess)
            { cudaGetLastError(); k_agg<<<(NN * 32 + 255) / 256, 256>>>(b2); } }

    {   cudaLaunchConfig_t c = cfg(2 * NSM, 256, DENSE_SMEM);
        if (cudaLaunchKernelEx(&c, k_dense, dW, db, oW) != cudaSuccess)
            { cudaGetLastError(); k_dense<<<2 * NSM, 256, DENSE_SMEM>>>(dW, db, oW); } }
    {   cudaLaunchConfig_t c = cfg((NSEL + 255) / 256, 256, 0);
        if (cudaLaunchKernelEx(&c, k_out, set_idx, out_edges, ob, out) != cudaSuccess)
            { cudaGetLastError(); k_out<<<(NSEL + 255) / 256, 256>>>(set_idx, out_edges, ob, out); } }
}

// round 13
// speedup vs baseline: 1.0190x; 1.0190x over previous
#include <cuda_runtime.h>

#define NN    50000
#define DD    128
#define EE    600000
#define NPRED 200000
#define NSEL  300000
#define UD    256
#define NB    49          // scan blocks: 49*1024 >= NN
#define NSM   148
#define NT64  ((NN + 63) / 64)   // 782 row-tiles

typedef unsigned long long ull;

// packed f32x2 helpers (sm_103a FFMA2 — only reachable via PTX)
#define FMA2(d, a, b) asm("fma.rn.f32x2 %0, %1, %2, %0;" : "+l"(d) : "l"(a), "l"(b))
#define UNPACK2(lo, hi, s) asm("mov.b64 {%0, %1}, %2;" : "=f"(lo), "=f"(hi) : "l"(s))

// ---------------- scratch (device globals: allocation-free) ----------------
__device__ int   g_deg_in[NN];
__device__ int   g_deg_out[NN];
__device__ float g_rin[NN];
__device__ float g_rout[NN];
__device__ int   g_off[NN + 1];
__device__ int   g_cur[NN];
__device__ int   g_srcs[EE];
__device__ int   g_bsum[NB];
__device__ float g_bufA[(size_t)NN * DD];
__device__ float g_bufB[(size_t)NN * DD];
__device__ float g_part[(size_t)NN * 4];   // [node][half*2 + {p0,p1}]

// ---------------- degree counting ----------------
__global__ void k_zero() {
    int i = blockIdx.x * blockDim.x + threadIdx.x;
    if (i < NN) { g_deg_in[i] = 0; g_deg_out[i] = 0; }
}

__global__ void k_count(const int* __restrict__ ei) {
    int e = blockIdx.x * blockDim.x + threadIdx.x;
    if (e < EE) {
        atomicAdd(&g_deg_out[ei[e]], 1);
        atomicAdd(&g_deg_in[ei[EE + e]], 1);
    }
}

// ---------------- scan pass A (+ fused rsqrt) ----------------
__global__ void k_scan_a() {
    __shared__ int wsum[32];
    int tid  = threadIdx.x;
    int i    = blockIdx.x * 1024 + tid;
    int lane = tid & 31, wid = tid >> 5;
    int v = (i < NN) ? g_deg_in[i] : 0;

    if (i < NN) {
        int dout = g_deg_out[i]; if (dout < 1) dout = 1;
        int din  = v;            if (din  < 1) din  = 1;
        g_rout[i] = rsqrtf((float)dout);
        g_rin[i]  = rsqrtf((float)din);
    }

    int x = v;
    #pragma unroll
    for (int s = 1; s < 32; s <<= 1) {
        int t = __shfl_up_sync(0xffffffffu, x, s);
        if (lane >= s) x += t;
    }
    if (lane == 31) wsum[wid] = x;
    __syncthreads();
    if (wid == 0) {
        int y = wsum[lane];
        #pragma unroll
        for (int s = 1; s < 32; s <<= 1) {
            int t = __shfl_up_sync(0xffffffffu, y, s);
            if (lane >= s) y += t;
        }
        wsum[lane] = y;
    }
    __syncthreads();

    int excl = x - v + (wid ? wsum[wid - 1] : 0);
    if (i < NN) g_off[i] = excl;
    if (tid == 1023) g_bsum[blockIdx.x] = excl + v;
}

// ---------------- scan pass C ----------------
__global__ void k_scan_c() {
    __shared__ int s_pre;
    int tid = threadIdx.x;
    if (tid == 0) {
        int run = 0;
        #pragma unroll
        for (int b = 0; b < NB; b++) {
            if (b == blockIdx.x) s_pre = run;
            run += g_bsum[b];
        }
        if (blockIdx.x == 0) g_off[NN] = run;
    }
    __syncthreads();
    int i = blockIdx.x * 1024 + tid;
    if (i < NN) {
        int o = g_off[i] + s_pre;
        g_off[i] = o;
        g_cur[i] = o;
    }
}

// ---------------- CSR fill ----------------
__global__ void k_fill(const int* __restrict__ ei) {
    int e = blockIdx.x * blockDim.x + threadIdx.x;
    if (e < EE) {
        int d = ei[EE + e];
        int slot = atomicAdd(&g_cur[d], 1);
        g_srcs[slot] = ei[e];
    }
}

// ---------------- conv GEMM (persistent, k-pair f32x2): dst = (X*rout)@W -----
// grid 2*NSM x 256 thr, 2 CTA/SM. A k-values loaded 4-wide (1 bcast LDS.128
// per row per kp-pair) -> LDS ~half of FMA2 issue: FMA2 is the sole bound.
__global__ void __launch_bounds__(256, 2)
k_gemm(const float* __restrict__ Xext, const float* __restrict__ W,
       float* __restrict__ dst, int useB) {
    extern __shared__ float sm[];
    float* Ws2 = sm;              // 64 kp x 128 cols x float2 (64 KB)
    float* Xs  = sm + DD * DD;    // 64 x 128
    const float* X = useB ? (const float*)g_bufB : Xext;

    int tid = threadIdx.x, wid = tid >> 5, lane = tid & 31;

    {   // stage W k-pair interleaved, once
        float2* Wd = (float2*)Ws2;
        #pragma unroll
        for (int q = 0; q < 32; q++) {
            int idx = tid + 256 * q;
            int kp = idx >> 7, c = idx & 127;
            Wd[idx] = make_float2(W[(2 * kp) * DD + c], W[(2 * kp + 1) * DD + c]);
        }
    }
    __syncthreads();
    const ull* Wp = (const ull*)Ws2;

    for (int tile = blockIdx.x; tile < NT64; tile += 2 * NSM) {
        int m0 = tile * 64;
        #pragma unroll
        for (int q = 0; q < 8; q++) {
            int gi = m0 + wid * 8 + q;
            float4 v = make_float4(0.f, 0.f, 0.f, 0.f);
            if (gi < NN) {
                v = *(const float4*)(X + (size_t)gi * DD + 4 * lane);
                float sc = g_rout[gi];
                v.x *= sc; v.y *= sc; v.z *= sc; v.w *= sc;
            }
            *(float4*)(Xs + (wid * 8 + q) * DD + 4 * lane) = v;
        }
        __syncwarp();

        ull acc[8][4];
        #pragma unroll
        for (int r = 0; r < 8; r++)
            #pragma unroll
            for (int c = 0; c < 4; c++) acc[r][c] = 0ull;

        #pragma unroll 2
        for (int kp2 = 0; kp2 < DD / 4; kp2++) {     // two k-pairs per iter
            const ull* base = Wp + (2 * kp2) * DD + 4 * lane;
            ulonglong2 b00 = *(const ulonglong2*)(base);
            ulonglong2 b01 = *(const ulonglong2*)(base + 2);
            ulonglong2 b10 = *(const ulonglong2*)(base + DD);
            ulonglong2 b11 = *(const ulonglong2*)(base + DD + 2);
            #pragma unroll
            for (int r = 0; r < 8; r++) {
                ulonglong2 aa = *(const ulonglong2*)(Xs + (wid * 8 + r) * DD + 4 * kp2);
                FMA2(acc[r][0], aa.x, b00.x);
                FMA2(acc[r][1], aa.x, b00.y);
                FMA2(acc[r][2], aa.x, b01.x);
                FMA2(acc[r][3], aa.x, b01.y);
                FMA2(acc[r][0], aa.y, b10.x);
                FMA2(acc[r][1], aa.y, b10.y);
                FMA2(acc[r][2], aa.y, b11.x);
                FMA2(acc[r][3], aa.y, b11.y);
            }
        }

        #pragma unroll
        for (int r = 0; r < 8; r++) {
            int gi = m0 + wid * 8 + r;
            if (gi < NN) {
                float4 o;
                float lo, hi;
                UNPACK2(lo, hi, acc[r][0]); o.x = lo + hi;
                UNPACK2(lo, hi, acc[r][1]); o.y = lo + hi;
                UNPACK2(lo, hi, acc[r][2]); o.z = lo + hi;
                UNPACK2(lo, hi, acc[r][3]); o.w = lo + hi;
                *(float4*)(dst + (size_t)gi * DD + 4 * lane) = o;
            }
        }
        __syncwarp();
    }
}

// ---------------- aggregation (separate, high-occupancy): bufB = rin*agg(bufA)+b
__global__ void k_agg(const float* __restrict__ bias) {
    int t = blockIdx.x * blockDim.x + threadIdx.x;
    int w = t >> 5, lane = t & 31;
    if (w >= NN) return;
    int lo = g_off[w], hi = g_off[w + 1];
    float4 acc = make_float4(0.f, 0.f, 0.f, 0.f);
    for (int j = lo; j < hi; j++) {
        int s = g_srcs[j];
        float4 v = *(const float4*)(g_bufA + (size_t)s * DD + lane * 4);
        acc.x += v.x; acc.y += v.y; acc.z += v.z; acc.w += v.w;
    }
    float r = g_rin[w];
    float4 bb = *(const float4*)(bias + lane * 4);
    float4 o;
    o.x = acc.x * r + bb.x; o.y = acc.y * r + bb.y;
    o.z = acc.z * r + bb.z; o.w = acc.w * r + bb.w;
    *(float4*)(g_bufB + (size_t)w * DD + lane * 4) = o;
}

// ---------------- dense head, HALF-SPLIT: 2 CTA/SM, each CTA owns 128 cols ---
__global__ void __launch_bounds__(256, 2)
k_dense(const float* __restrict__ dW,
        const float* __restrict__ db,
        const float* __restrict__ oW) {
    extern __shared__ float sm[];
    float* Ws2  = sm;                  // 64 kp x 128 cols x float2 (64 KB)
    float* Xs   = Ws2 + DD * DD;       // 64 x 128 (32 KB)
    float* s_db = Xs + 64 * DD;        // 128
    float* s_oW = s_db + 128;          // 256

    int tid  = threadIdx.x, wid = tid >> 5, lane = tid & 31;
    int half = blockIdx.x & 1;
    int cbase = half * 128;

    {   // stage this half of dense_W, k-pair interleaved
        float2* Wd = (float2*)Ws2;
        #pragma unroll
        for (int q = 0; q < 32; q++) {
            int idx = tid + 256 * q;          // 0..8191
            int kp = idx >> 7, c = idx & 127;
            Wd[idx] = make_float2(dW[(2 * kp) * UD + cbase + c],
                                  dW[(2 * kp + 1) * UD + cbase + c]);
        }
    }
    if (tid < 128) {
        s_db[tid]         = db[cbase + tid];
        s_oW[tid * 2]     = oW[(cbase + tid) * 2];
        s_oW[tid * 2 + 1] = oW[(cbase + tid) * 2 + 1];
    }
    __syncthreads();
    const ull* Wp = (const ull*)Ws2;

    for (int tile = blockIdx.x >> 1; tile < NT64; tile += NSM) {
        int m0 = tile * 64;
        #pragma unroll
        for (int q = 0; q < 8; q++) {
            int gi = m0 + wid * 8 + q;
            float4 v = make_float4(0.f, 0.f, 0.f, 0.f);
            if (gi < NN)
                v = *(const float4*)(g_bufB + (size_t)gi * DD + 4 * lane);
            *(float4*)(Xs + (wid * 8 + q) * DD + 4 * lane) = v;
        }
        __syncwarp();

        ull acc[8][4];
        #pragma unroll
        for (int r = 0; r < 8; r++)
            #pragma unroll
            for (int c = 0; c < 4; c++) acc[r][c] = 0ull;

        #pragma unroll 2
        for (int kp2 = 0; kp2 < DD / 4; kp2++) {
            const ull* base = Wp + (2 * kp2) * DD + 4 * lane;
            ulonglong2 b00 = *(const ulonglong2*)(base);
            ulonglong2 b01 = *(const ulonglong2*)(base + 2);
            ulonglong2 b10 = *(const ulonglong2*)(base + DD);
            ulonglong2 b11 = *(const ulonglong2*)(base + DD + 2);
            #pragma unroll
            for (int r = 0; r < 8; r++) {
                ulonglong2 aa = *(const ulonglong2*)(Xs + (wid * 8 + r) * DD + 4 * kp2);
                FMA2(acc[r][0], aa.x, b00.x);
                FMA2(acc[r][1], aa.x, b00.y);
                FMA2(acc[r][2], aa.x, b01.x);
                FMA2(acc[r][3], aa.x, b01.y);
                FMA2(acc[r][0], aa.y, b10.x);
                FMA2(acc[r][1], aa.y, b10.y);
                FMA2(acc[r][2], aa.y, b11.x);
                FMA2(acc[r][3], aa.y, b11.y);
            }
        }

        // epilogue: relu + partial 128->2, warp reduce, write g_part
        #pragma unroll
        for (int r = 0; r < 8; r++) {
            float p0 = 0.f, p1 = 0.f;
            #pragma unroll
            for (int c = 0; c < 4; c++) {
                float lo, hi;
                UNPACK2(lo, hi, acc[r][c]);
                int col = 4 * lane + c;               // col within half
                float v = fmaxf(lo + hi + s_db[col], 0.f);
                p0 = fmaf(v, s_oW[col * 2],     p0);
                p1 = fmaf(v, s_oW[col * 2 + 1], p1);
            }
            #pragma unroll
            for (int o = 16; o; o >>= 1) {
                p0 += __shfl_down_sync(0xffffffffu, p0, o);
                p1 += __shfl_down_sync(0xffffffffu, p1, o);
            }
            if (lane == 0) {
                int gi = m0 + wid * 8 + r;
                if (gi < NN)
                    *(float2*)(g_part + (size_t)gi * 4 + half * 2) = make_float2(p0, p1);
            }
        }
        __syncwarp();
    }
}

// ---------------- output: combine halves + ob + softmax + gather -------------
__global__ void k_out(const int* __restrict__ set_idx,
                      const int* __restrict__ oe,
                      const float* __restrict__ ob,
                      float* __restrict__ out) {
    int i = blockIdx.x * blockDim.x + threadIdx.x;
    if (i < NSEL) {
        int node = oe[set_idx[i]];
        float4 pt = *(const float4*)(g_part + (size_t)node * 4);
        float z0 = pt.x + pt.z + ob[0];
        float z1 = pt.y + pt.w + ob[1];
        float m  = fmaxf(z0, z1);
        float e0 = __expf(z0 - m), e1 = __expf(z1 - m);
        float inv = 1.f / (e0 + e1);
        *(float2*)(out + (size_t)i * 2) = make_float2(e0 * inv, e1 * inv);
    }
}

// ---------------- host launch ----------------
extern "C" void kernel_launch(void* const* d_in, const int* in_sizes, int n_in,
                              void* d_out, int out_size) {
    const float* node_state = (const float*)d_in[0];
    const int*   edge_index = (const int*)d_in[1];
    const int*   out_edges  = (const int*)d_in[2];
    const int*   set_idx    = (const int*)d_in[3];
    const float* W1         = (const float*)d_in[4];
    const float* b1         = (const float*)d_in[5];
    const float* W2         = (const float*)d_in[6];
    const float* b2         = (const float*)d_in[7];
    const float* dW         = (const float*)d_in[8];
    const float* db         = (const float*)d_in[9];
    const float* oW         = (const float*)d_in[10];
    const float* ob         = (const float*)d_in[11];
    float* out = (float*)d_out;

    const int GEMM_SMEM  = (DD * DD + 64 * DD) * 4;                // 96 KB
    const int DENSE_SMEM = (DD * DD + 64 * DD + 128 + 256) * 4;    // ~97.5 KB

    cudaFuncSetAttribute(k_gemm,  cudaFuncAttributeMaxDynamicSharedMemorySize, GEMM_SMEM);
    cudaFuncSetAttribute(k_dense, cudaFuncAttributeMaxDynamicSharedMemorySize, DENSE_SMEM);

    float* bufA = nullptr; float* bufB = nullptr;
    cudaGetSymbolAddress((void**)&bufA, g_bufA);
    cudaGetSymbolAddress((void**)&bufB, g_bufB);

    k_zero   <<<(NN + 255) / 256, 256>>>();
    k_count  <<<(EE + 255) / 256, 256>>>(edge_index);
    k_scan_a <<<NB, 1024>>>();
    k_scan_c <<<NB, 1024>>>();
    k_fill   <<<(EE + 255) / 256, 256>>>(edge_index);

    // layer 1: bufA = (X*rout)@W1 ; bufB = rin*agg(bufA)+b1
    k_gemm<<<2 * NSM, 256, GEMM_SMEM>>>(node_state, W1, bufA, 0);
    k_agg <<<(NN * 32 + 255) / 256, 256>>>(b1);
    // layer 2: bufA = (bufB*rout)@W2 ; bufB = rin*agg(bufA)+b2  (h2)
    k_gemm<<<2 * NSM, 256, GEMM_SMEM>>>(nullptr, W2, bufA, 1);
    k_agg <<<(NN * 32 + 255) / 256, 256>>>(b2);

    // dense head (half-split, 2 CTA/SM) + combine/softmax/gather
    k_dense<<<2 * NSM, 256, DENSE_SMEM>>>(dW, db, oW);
    k_out  <<<(NSEL + 255) / 256, 256>>>(set_idx, out_edges, ob, out);
}

// round 14
// speedup vs baseline: 1.1722x; 1.1504x over previous
#include <cuda_runtime.h>

#define NN    50000
#define DD    128
#define EE    600000
#define NPRED 200000
#define NSEL  300000
#define UD    256
#define NB    49          // scan blocks: 49*1024 >= NN
#define NSM   148
#define NT64  ((NN + 63) / 64)   // 782 row-tiles

typedef unsigned long long ull;

// packed f32x2 helpers (sm_103a FFMA2 — only reachable via PTX)
#define FMA2(d, a, b) asm("fma.rn.f32x2 %0, %1, %2, %0;" : "+l"(d) : "l"(a), "l"(b))
#define UNPACK2(lo, hi, s) asm("mov.b64 {%0, %1}, %2;" : "=f"(lo), "=f"(hi) : "l"(s))

// ---------------- scratch (device globals: allocation-free) ----------------
__device__ int   g_deg_in[NN];
__device__ int   g_deg_out[NN];
__device__ float g_rin[NN];
__device__ float g_rout[NN];
__device__ int   g_off[NN + 1];
__device__ int   g_cur[NN];
__device__ int   g_srcs[EE];
__device__ int   g_bsum[NB];
__device__ float g_Wc[DD * DD];           // W1 @ W2
__device__ float g_c1[DD];                // b1 @ W2
__device__ float g_srin[NN];              // rin[i] * sum_{s in in(i)} rout[s]
__device__ float g_bufA[(size_t)NN * DD];
__device__ float g_bufB[(size_t)NN * DD];
__device__ float g_part[(size_t)NN * 4];  // [node][half*2 + {p0,p1}]

// ---------------- combined weights: Wc = W1@W2, c1 = b1@W2 ----------------
// 129 blocks x 128 threads: block b<128 -> row b of Wc; block 128 -> c1.
__global__ void k_wc(const float* __restrict__ W1, const float* __restrict__ W2,
                     const float* __restrict__ b1) {
    __shared__ float row[DD];
    int b = blockIdx.x;
    int j = threadIdx.x;
    row[j] = (b < DD) ? W1[b * DD + j] : b1[j];
    __syncthreads();
    float acc = 0.f;
    #pragma unroll 8
    for (int k = 0; k < DD; k++)
        acc = fmaf(row[k], W2[k * DD + j], acc);
    if (b < DD) g_Wc[b * DD + j] = acc;
    else        g_c1[j] = acc;
}

// ---------------- degree counting ----------------
__global__ void k_zero() {
    int i = blockIdx.x * blockDim.x + threadIdx.x;
    if (i < NN) { g_deg_in[i] = 0; g_deg_out[i] = 0; }
}

__global__ void k_count(const int* __restrict__ ei) {
    int e = blockIdx.x * blockDim.x + threadIdx.x;
    if (e < EE) {
        atomicAdd(&g_deg_out[ei[e]], 1);
        atomicAdd(&g_deg_in[ei[EE + e]], 1);
    }
}

// ---------------- scan pass A (+ fused rsqrt) ----------------
__global__ void k_scan_a() {
    __shared__ int wsum[32];
    int tid  = threadIdx.x;
    int i    = blockIdx.x * 1024 + tid;
    int lane = tid & 31, wid = tid >> 5;
    int v = (i < NN) ? g_deg_in[i] : 0;

    if (i < NN) {
        int dout = g_deg_out[i]; if (dout < 1) dout = 1;
        int din  = v;            if (din  < 1) din  = 1;
        g_rout[i] = rsqrtf((float)dout);
        g_rin[i]  = rsqrtf((float)din);
    }

    int x = v;
    #pragma unroll
    for (int s = 1; s < 32; s <<= 1) {
        int t = __shfl_up_sync(0xffffffffu, x, s);
        if (lane >= s) x += t;
    }
    if (lane == 31) wsum[wid] = x;
    __syncthreads();
    if (wid == 0) {
        int y = wsum[lane];
        #pragma unroll
        for (int s = 1; s < 32; s <<= 1) {
            int t = __shfl_up_sync(0xffffffffu, y, s);
            if (lane >= s) y += t;
        }
        wsum[lane] = y;
    }
    __syncthreads();

    int excl = x - v + (wid ? wsum[wid - 1] : 0);
    if (i < NN) g_off[i] = excl;
    if (tid == 1023) g_bsum[blockIdx.x] = excl + v;
}

// ---------------- scan pass C ----------------
__global__ void k_scan_c() {
    __shared__ int s_pre;
    int tid = threadIdx.x;
    if (tid == 0) {
        int run = 0;
        #pragma unroll
        for (int b = 0; b < NB; b++) {
            if (b == blockIdx.x) s_pre = run;
            run += g_bsum[b];
        }
        if (blockIdx.x == 0) g_off[NN] = run;
    }
    __syncthreads();
    int i = blockIdx.x * 1024 + tid;
    if (i < NN) {
        int o = g_off[i] + s_pre;
        g_off[i] = o;
        g_cur[i] = o;
    }
}

// ---------------- CSR fill ----------------
__global__ void k_fill(const int* __restrict__ ei) {
    int e = blockIdx.x * blockDim.x + threadIdx.x;
    if (e < EE) {
        int d = ei[EE + e];
        int slot = atomicAdd(&g_cur[d], 1);
        g_srcs[slot] = ei[e];
    }
}

// ---------------- aggA: bufA[i] = rout[i]*rin[i] * sum rout[s]*X[s] ----------
__global__ void k_aggA(const float* __restrict__ X) {
    int t = blockIdx.x * blockDim.x + threadIdx.x;
    int w = t >> 5, lane = t & 31;
    if (w >= NN) return;
    int lo = g_off[w], hi = g_off[w + 1];
    float4 acc = make_float4(0.f, 0.f, 0.f, 0.f);
    for (int j = lo; j < hi; j++) {
        int s = g_srcs[j];
        float r = g_rout[s];
        float4 v = *(const float4*)(X + (size_t)s * DD + lane * 4);
        acc.x = fmaf(r, v.x, acc.x);
        acc.y = fmaf(r, v.y, acc.y);
        acc.z = fmaf(r, v.z, acc.z);
        acc.w = fmaf(r, v.w, acc.w);
    }
    float sc = g_rout[w] * g_rin[w];
    float4 o;
    o.x = acc.x * sc; o.y = acc.y * sc; o.z = acc.z * sc; o.w = acc.w * sc;
    *(float4*)(g_bufA + (size_t)w * DD + lane * 4) = o;
}

// ---------------- aggB: bufB[i] = sum bufA[s] ; srin[i] = rin[i]*sum rout[s] --
__global__ void k_aggB() {
    int t = blockIdx.x * blockDim.x + threadIdx.x;
    int w = t >> 5, lane = t & 31;
    if (w >= NN) return;
    int lo = g_off[w], hi = g_off[w + 1];
    float4 acc = make_float4(0.f, 0.f, 0.f, 0.f);
    float ss = 0.f;
    for (int j = lo; j < hi; j++) {
        int s = g_srcs[j];
        ss += g_rout[s];
        float4 v = *(const float4*)(g_bufA + (size_t)s * DD + lane * 4);
        acc.x += v.x; acc.y += v.y; acc.z += v.z; acc.w += v.w;
    }
    *(float4*)(g_bufB + (size_t)w * DD + lane * 4) = acc;
    if (lane == 0) g_srin[w] = g_rin[w] * ss;
}

// ---------------- conv GEMM (persistent, round-11 mainloop) ------------------
// h2 = rin*(B@Wc) + srin*c1 + b2 ; B rows in bufB, h2 written to bufA.
__global__ void __launch_bounds__(256, 2)
k_conv(const float* __restrict__ b2) {
    extern __shared__ float sm[];
    float* Ws2 = sm;              // 64 kp x 128 cols x float2 (64 KB)
    float* Xs  = sm + DD * DD;    // 64 x 128

    int tid = threadIdx.x, wid = tid >> 5, lane = tid & 31;

    {   // stage Wc k-pair interleaved, once
        float2* Wd = (float2*)Ws2;
        #pragma unroll
        for (int q = 0; q < 32; q++) {
            int idx = tid + 256 * q;
            int kp = idx >> 7, c = idx & 127;
            Wd[idx] = make_float2(g_Wc[(2 * kp) * DD + c], g_Wc[(2 * kp + 1) * DD + c]);
        }
    }
    __syncthreads();
    const ull* Wp = (const ull*)Ws2;
    float4 c1v = *(const float4*)(g_c1 + 4 * lane);
    float4 b2v = *(const float4*)(b2 + 4 * lane);

    for (int tile = blockIdx.x; tile < NT64; tile += 2 * NSM) {
        int m0 = tile * 64;
        #pragma unroll
        for (int q = 0; q < 8; q++) {
            int gi = m0 + wid * 8 + q;
            float4 v = make_float4(0.f, 0.f, 0.f, 0.f);
            if (gi < NN)
                v = *(const float4*)(g_bufB + (size_t)gi * DD + 4 * lane);
            *(float4*)(Xs + (wid * 8 + q) * DD + 4 * lane) = v;
        }
        __syncwarp();

        ull acc[8][4];
        #pragma unroll
        for (int r = 0; r < 8; r++)
            #pragma unroll
            for (int c = 0; c < 4; c++) acc[r][c] = 0ull;

        #pragma unroll 8
        for (int kp = 0; kp < DD / 2; kp++) {
            ulonglong2 bb0 = *(const ulonglong2*)(Wp + kp * DD + 4 * lane);
            ulonglong2 bb1 = *(const ulonglong2*)(Wp + kp * DD + 4 * lane + 2);
            ull a2[8];
            #pragma unroll
            for (int r = 0; r < 8; r++)
                a2[r] = *(const ull*)(Xs + (wid * 8 + r) * DD + 2 * kp);  // broadcast
            #pragma unroll
            for (int r = 0; r < 8; r++) {
                FMA2(acc[r][0], a2[r], bb0.x);
                FMA2(acc[r][1], a2[r], bb0.y);
                FMA2(acc[r][2], a2[r], bb1.x);
                FMA2(acc[r][3], a2[r], bb1.y);
            }
        }

        #pragma unroll
        for (int r = 0; r < 8; r++) {
            int gi = m0 + wid * 8 + r;
            if (gi < NN) {
                float ri = g_rin[gi];
                float sr = g_srin[gi];
                float4 o;
                float lo, hi;
                UNPACK2(lo, hi, acc[r][0]); o.x = (lo + hi) * ri + sr * c1v.x + b2v.x;
                UNPACK2(lo, hi, acc[r][1]); o.y = (lo + hi) * ri + sr * c1v.y + b2v.y;
                UNPACK2(lo, hi, acc[r][2]); o.z = (lo + hi) * ri + sr * c1v.z + b2v.z;
                UNPACK2(lo, hi, acc[r][3]); o.w = (lo + hi) * ri + sr * c1v.w + b2v.w;
                *(float4*)(g_bufA + (size_t)gi * DD + 4 * lane) = o;
            }
        }
        __syncwarp();
    }
}

// ---------------- dense head, HALF-SPLIT (round-11; reads bufA) --------------
__global__ void __launch_bounds__(256, 2)
k_dense(const float* __restrict__ dW,
        const float* __restrict__ db,
        const float* __restrict__ oW) {
    extern __shared__ float sm[];
    float* Ws2  = sm;                  // 64 kp x 128 cols x float2 (64 KB)
    float* Xs   = Ws2 + DD * DD;       // 64 x 128 (32 KB)
    float* s_db = Xs + 64 * DD;        // 128
    float* s_oW = s_db + 128;          // 256

    int tid  = threadIdx.x, wid = tid >> 5, lane = tid & 31;
    int half = blockIdx.x & 1;
    int cbase = half * 128;

    {   // stage this half of dense_W, k-pair interleaved
        float2* Wd = (float2*)Ws2;
        #pragma unroll
        for (int q = 0; q < 32; q++) {
            int idx = tid + 256 * q;          // 0..8191
            int kp = idx >> 7, c = idx & 127;
            Wd[idx] = make_float2(dW[(2 * kp) * UD + cbase + c],
                                  dW[(2 * kp + 1) * UD + cbase + c]);
        }
    }
    if (tid < 128) {
        s_db[tid]         = db[cbase + tid];
        s_oW[tid * 2]     = oW[(cbase + tid) * 2];
        s_oW[tid * 2 + 1] = oW[(cbase + tid) * 2 + 1];
    }
    __syncthreads();
    const ull* Wp = (const ull*)Ws2;

    for (int tile = blockIdx.x >> 1; tile < NT64; tile += NSM) {
        int m0 = tile * 64;
        #pragma unroll
        for (int q = 0; q < 8; q++) {
            int gi = m0 + wid * 8 + q;
            float4 v = make_float4(0.f, 0.f, 0.f, 0.f);
            if (gi < NN)
                v = *(const float4*)(g_bufA + (size_t)gi * DD + 4 * lane);
            *(float4*)(Xs + (wid * 8 + q) * DD + 4 * lane) = v;
        }
        __syncwarp();

        ull acc[8][4];
        #pragma unroll
        for (int r = 0; r < 8; r++)
            #pragma unroll
            for (int c = 0; c < 4; c++) acc[r][c] = 0ull;

        #pragma unroll 8
        for (int kp = 0; kp < DD / 2; kp++) {
            ulonglong2 bb0 = *(const ulonglong2*)(Wp + kp * DD + 4 * lane);
            ulonglong2 bb1 = *(const ulonglong2*)(Wp + kp * DD + 4 * lane + 2);
            ull a2[8];
            #pragma unroll
            for (int r = 0; r < 8; r++)
                a2[r] = *(const ull*)(Xs + (wid * 8 + r) * DD + 2 * kp);  // broadcast
            #pragma unroll
            for (int r = 0; r < 8; r++) {
                FMA2(acc[r][0], a2[r], bb0.x);
                FMA2(acc[r][1], a2[r], bb0.y);
                FMA2(acc[r][2], a2[r], bb1.x);
                FMA2(acc[r][3], a2[r], bb1.y);
            }
        }

        // epilogue: relu + partial 128->2, warp reduce, write g_part
        #pragma unroll
        for (int r = 0; r < 8; r++) {
            float p0 = 0.f, p1 = 0.f;
            #pragma unroll
            for (int c = 0; c < 4; c++) {
                float lo, hi;
                UNPACK2(lo, hi, acc[r][c]);
                int col = 4 * lane + c;               // col within half
                float v = fmaxf(lo + hi + s_db[col], 0.f);
                p0 = fmaf(v, s_oW[col * 2],     p0);
                p1 = fmaf(v, s_oW[col * 2 + 1], p1);
            }
            #pragma unroll
            for (int o = 16; o; o >>= 1) {
                p0 += __shfl_down_sync(0xffffffffu, p0, o);
                p1 += __shfl_down_sync(0xffffffffu, p1, o);
            }
            if (lane == 0) {
                int gi = m0 + wid * 8 + r;
                if (gi < NN)
                    *(float2*)(g_part + (size_t)gi * 4 + half * 2) = make_float2(p0, p1);
            }
        }
        __syncwarp();
    }
}

// ---------------- output: combine halves + ob + softmax + gather -------------
__global__ void k_out(const int* __restrict__ set_idx,
                      const int* __restrict__ oe,
                      const float* __restrict__ ob,
                      float* __restrict__ out) {
    int i = blockIdx.x * blockDim.x + threadIdx.x;
    if (i < NSEL) {
        int node = oe[set_idx[i]];
        float4 pt = *(const float4*)(g_part + (size_t)node * 4);
        float z0 = pt.x + pt.z + ob[0];
        float z1 = pt.y + pt.w + ob[1];
        float m  = fmaxf(z0, z1);
        float e0 = __expf(z0 - m), e1 = __expf(z1 - m);
        float inv = 1.f / (e0 + e1);
        *(float2*)(out + (size_t)i * 2) = make_float2(e0 * inv, e1 * inv);
    }
}

// ---------------- host launch ----------------
extern "C" void kernel_launch(void* const* d_in, const int* in_sizes, int n_in,
                              void* d_out, int out_size) {
    const float* node_state = (const float*)d_in[0];
    const int*   edge_index = (const int*)d_in[1];
    const int*   out_edges  = (const int*)d_in[2];
    const int*   set_idx    = (const int*)d_in[3];
    const float* W1         = (const float*)d_in[4];
    const float* b1         = (const float*)d_in[5];
    const float* W2         = (const float*)d_in[6];
    const float* b2         = (const float*)d_in[7];
    const float* dW         = (const float*)d_in[8];
    const float* db         = (const float*)d_in[9];
    const float* oW         = (const float*)d_in[10];
    const float* ob         = (const float*)d_in[11];
    float* out = (float*)d_out;

    const int GEMM_SMEM  = (DD * DD + 64 * DD) * 4;                // 96 KB
    const int DENSE_SMEM = (DD * DD + 64 * DD + 128 + 256) * 4;    // ~97.5 KB

    cudaFuncSetAttribute(k_conv,  cudaFuncAttributeMaxDynamicSharedMemorySize, GEMM_SMEM);
    cudaFuncSetAttribute(k_dense, cudaFuncAttributeMaxDynamicSharedMemorySize, DENSE_SMEM);

    k_wc     <<<DD + 1, DD>>>(W1, W2, b1);     // Wc = W1@W2, c1 = b1@W2
    k_zero   <<<(NN + 255) / 256, 256>>>();
    k_count  <<<(EE + 255) / 256, 256>>>(edge_index);
    k_scan_a <<<NB, 1024>>>();
    k_scan_c <<<NB, 1024>>>();
    k_fill   <<<(EE + 255) / 256, 256>>>(edge_index);

    // collapsed conv layers:
    k_aggA<<<(NN * 32 + 255) / 256, 256>>>(node_state);  // bufA = rout*rin*agg(rout*X)
    k_aggB<<<(NN * 32 + 255) / 256, 256>>>();            // bufB = agg(bufA), srin
    k_conv<<<2 * NSM, 256, GEMM_SMEM>>>(b2);             // bufA = h2

    // dense head (half-split) + combine/softmax/gather
    k_dense<<<2 * NSM, 256, DENSE_SMEM>>>(dW, db, oW);
    k_out  <<<(NSEL + 255) / 256, 256>>>(set_idx, out_edges, ob, out);
}